// round 13
// baseline (speedup 1.0000x reference)
#include <cuda_runtime.h>
#include <cuda_fp16.h>
#include <cstdint>
#include <math.h>

#define D_  512
#define NB_ 2048
#define TT_ 64
#define MT_ (NB_*TT_)

#define ATILE 16384        // 128r x 64k fp16 hi-only, SW128
#define NKT 8

__device__ __align__(128) unsigned char g_Ximg[(size_t)1024 * NKT * ATILE];
__device__ __align__(128) unsigned char g_W1img[12 * NKT * ATILE];   // hi-only
__device__ __align__(128) unsigned char g_Wgimg[8 * NKT * ATILE];    // hi-only
__device__ __align__(128) unsigned char g_Whimg[4 * NKT * ATILE];    // hi-only
__device__ __align__(128) unsigned char g_Himg[16 * NKT * ATILE];
__device__ __align__(128) unsigned char g_Uimg[16 * NKT * ATILE];
__device__ __align__(16) __half g_xp16[(size_t)MT_ * 1536];          // fp16 xproj
__device__ __align__(16) float g_bias[1536];
__device__ __align__(16) float g_h[NB_ * D_];
__device__ __align__(16) float g_z[NB_ * D_];

// ---------------- helpers ----------------
__device__ __forceinline__ uint32_t swz(uint32_t o) { return o ^ ((o >> 3) & 0x70); }

__device__ __forceinline__ uint32_t pack_hi(float x0, float x1) {
    __half2 h = __floats2half2_rn(x0, x1);
    return *reinterpret_cast<uint32_t*>(&h);
}
__device__ __forceinline__ float2 unpack_h2(uint32_t u) {
    __half2 h = *reinterpret_cast<__half2*>(&u);
    return __half22float2(h);
}

__device__ __forceinline__ void aimg_write(unsigned char* img, int rt, int kt,
                                           int irow, int jj, float x0, float x1) {
    size_t blk = ((size_t)rt * NKT + kt) * ATILE;
    uint32_t off = swz((uint32_t)irow * 128 + (uint32_t)jj * 4);
    *(uint32_t*)(img + blk + off) = pack_hi(x0, x1);
}

__device__ __forceinline__ uint32_t smem_u32(const void* p) {
    uint32_t r;
    asm("{ .reg .u64 t; cvta.to.shared.u64 t, %1; cvt.u32.u64 %0, t; }" : "=r"(r) : "l"(p));
    return r;
}
__device__ __forceinline__ void cpa16(uint32_t dst, const void* src) {
    asm volatile("cp.async.cg.shared.global [%0], [%1], 16;" :: "r"(dst), "l"(src));
}
__device__ __forceinline__ void cpa_commit() { asm volatile("cp.async.commit_group;" ::: "memory"); }
__device__ __forceinline__ void cpa_wait0() { asm volatile("cp.async.wait_group 0;" ::: "memory"); }
__device__ __forceinline__ void pref_l2(const void* p) {
    asm volatile("prefetch.global.L2 [%0];" :: "l"(p));
}
__device__ __forceinline__ void cl_arrive() { asm volatile("barrier.cluster.arrive.aligned;" ::: "memory"); }
__device__ __forceinline__ void cl_wait()   { asm volatile("barrier.cluster.wait.aligned;" ::: "memory"); }

__device__ __forceinline__ void ldsm4(uint32_t* r, uint32_t addr) {
    asm volatile("ldmatrix.sync.aligned.m8n8.x4.shared.b16 {%0,%1,%2,%3}, [%4];"
                 : "=r"(r[0]), "=r"(r[1]), "=r"(r[2]), "=r"(r[3]) : "r"(addr));
}
__device__ __forceinline__ void mma16(float* d, const uint32_t* a, const uint32_t* b) {
    asm volatile(
        "mma.sync.aligned.m16n8k16.row.col.f32.f16.f16.f32 "
        "{%0,%1,%2,%3},{%4,%5,%6,%7},{%8,%9},{%0,%1,%2,%3};"
        : "+f"(d[0]), "+f"(d[1]), "+f"(d[2]), "+f"(d[3])
        : "r"(a[0]), "r"(a[1]), "r"(a[2]), "r"(a[3]), "r"(b[0]), "r"(b[1]));
}
__device__ __forceinline__ float sigmoidf_(float x) { return 1.0f / (1.0f + expf(-x)); }

// ---------------- prep ----------------
__global__ void prep_weights(const float* __restrict__ Wzx, const float* __restrict__ Wzh,
                             const float* __restrict__ Wrx, const float* __restrict__ Wrh,
                             const float* __restrict__ Whx, const float* __restrict__ Whh,
                             const float* __restrict__ bz, const float* __restrict__ br,
                             const float* __restrict__ bh) {
    int i = blockIdx.x * 256 + threadIdx.x;
    int n = i >> 8, jp = i & 255;
    int kt = jp >> 5, jj = jp & 31, k = jp * 2;
    {
        const float* s = (n < 512) ? Wzx : (n < 1024 ? Wrx : Whx);
        int nn = (n < 512) ? n : (n < 1024 ? n - 512 : n - 1024);
        aimg_write(g_W1img, n >> 7, kt, n & 127, jj, s[nn * 512 + k], s[nn * 512 + k + 1]);
    }
    if (n < 1024) {
        const float* s = (n < 512) ? Wzh : Wrh;
        int nn = n & 511;
        aimg_write(g_Wgimg, n >> 7, kt, n & 127, jj, s[nn * 512 + k], s[nn * 512 + k + 1]);
    }
    if (n < 512)
        aimg_write(g_Whimg, n >> 7, kt, n & 127, jj, Whh[n * 512 + k], Whh[n * 512 + k + 1]);
    if (i < 1536) g_bias[i] = (i < 512) ? bz[i] : (i < 1024 ? br[i - 512] : bh[i - 1024]);
    if (i < NB_ * D_ / 4) ((float4*)g_h)[i] = make_float4(0.f, 0.f, 0.f, 0.f);
    if (i < 16 * NKT * ATILE / 16) ((uint4*)g_Himg)[i] = make_uint4(0, 0, 0, 0);
}

__global__ void prep_x(const float* __restrict__ X) {
    int i = blockIdx.x * 256 + threadIdx.x;      // 32768 blocks; 8 cols per thread
    int row = i >> 6, jq = i & 63;
    const float* src = X + (size_t)row * 512 + jq * 8;
    float4 a = *(const float4*)src, b = *(const float4*)(src + 4);
    uint4 v = make_uint4(pack_hi(a.x, a.y), pack_hi(a.z, a.w),
                         pack_hi(b.x, b.y), pack_hi(b.z, b.w));
    int kt = jq >> 3;
    size_t blk = ((size_t)(row >> 7) * NKT + kt) * ATILE;
    uint32_t off = swz((uint32_t)(row & 127) * 128 + (uint32_t)(jq & 7) * 16);
    *(uint4*)(g_Ximg + blk + off) = v;
}

// ---------------- gemm0 core ----------
__device__ __forceinline__ void gemm0_core(uint32_t smb,
                                           const unsigned char* __restrict__ Asrc0,
                                           const unsigned char* __restrict__ Bsrc0,
                                           float (*acc)[4]) {
    constexpr int SBUF = 32768;
    const int tid = threadIdx.x, lane = tid & 31, warp = tid >> 5;
    const int wm = warp >> 2, wn = warp & 3;
    const int rx = (lane & 7) << 4;
    const int colA = (lane >> 4) << 4;
    const int colB = ((lane >> 3) & 1) << 4;
    int rA[2], rB[2];
#pragma unroll
    for (int mt = 0; mt < 2; mt++)
        rA[mt] = (wm * 32 + mt * 16 + (lane & 15)) * 128;
#pragma unroll
    for (int p = 0; p < 2; p++)
        rB[p] = (wn * 32 + p * 16 + (lane & 7) + ((lane >> 4) << 3)) * 128;

    auto docopy = [&](int kt) {
        const uint32_t da = smb + (kt & 1) * SBUF;
        const unsigned char* sa = Asrc0 + (size_t)kt * ATILE;
        cpa16(da + tid * 16, sa + (size_t)tid * 16);
        cpa16(da + (tid + 512) * 16, sa + (size_t)(tid + 512) * 16);
        const uint32_t db = da + 16384;
        const unsigned char* sb = Bsrc0 + (size_t)kt * ATILE;
        cpa16(db + tid * 16, sb + (size_t)tid * 16);
        cpa16(db + (tid + 512) * 16, sb + (size_t)(tid + 512) * 16);
    };

    docopy(0); cpa_commit();
#pragma unroll 1
    for (int kt = 0; kt < NKT; kt++) {
        cpa_wait0();
        __syncthreads();
        if (kt < NKT - 1) { docopy(kt + 1); cpa_commit(); }

        const uint32_t sA = smb + (kt & 1) * SBUF;
        const uint32_t sB = sA + 16384;
#pragma unroll
        for (int k16 = 0; k16 < 4; k16++) {
            uint32_t Ah[2][4];
#pragma unroll
            for (int mt = 0; mt < 2; mt++)
                ldsm4(Ah[mt], sA + rA[mt] + ((k16 * 32 + colA) ^ rx));
            uint32_t Bh[4][2];
#pragma unroll
            for (int p = 0; p < 2; p++) {
                uint32_t r4[4];
                ldsm4(r4, sB + rB[p] + ((k16 * 32 + colB) ^ rx));
                Bh[2 * p][0] = r4[0]; Bh[2 * p][1] = r4[1];
                Bh[2 * p + 1][0] = r4[2]; Bh[2 * p + 1][1] = r4[3];
            }
#pragma unroll
            for (int mt = 0; mt < 2; mt++)
#pragma unroll
                for (int nt = 0; nt < 4; nt++) mma16(acc[mt * 4 + nt], Ah[mt], Bh[nt]);
        }
    }
}

// ---------------- phase-1 kernel ----------------
__global__ __launch_bounds__(512, 1) void gemm0_k(float* __restrict__ out) {
    extern __shared__ __align__(1024) unsigned char sm[];
    const uint32_t smb = smem_u32(sm);
    const int tid = threadIdx.x, lane = tid & 31, warp = tid >> 5;
    const int wm = warp >> 2, wn = warp & 3, g = lane >> 2, tg = lane & 3;
    const int bn = blockIdx.x, bm = blockIdx.y;

    float acc[8][4];
#pragma unroll
    for (int i = 0; i < 8; i++)
#pragma unroll
        for (int e = 0; e < 4; e++) acc[i][e] = 0.0f;

    gemm0_core(smb, g_Ximg + (size_t)bm * NKT * ATILE,
               g_W1img + (size_t)bn * NKT * ATILE, acc);

    const int cbase = bn * 128 + wn * 32;
#pragma unroll
    for (int mt = 0; mt < 2; mt++)
#pragma unroll
        for (int nt = 0; nt < 4; nt++) {
            const int c = cbase + nt * 8 + tg * 2;
            float2 b = *(const float2*)(g_bias + c);
#pragma unroll
            for (int h2 = 0; h2 < 2; h2++) {
                const int row = bm * 128 + wm * 32 + mt * 16 + g + h2 * 8;
                float o0 = acc[mt * 4 + nt][h2 * 2 + 0] + b.x;
                float o1 = acc[mt * 4 + nt][h2 * 2 + 1] + b.y;
                *(uint32_t*)(g_xp16 + (size_t)row * 1536 + c) = pack_hi(o0, o1);
            }
        }
}

// ---------------- persistent recurrence (cluster = 8-CTA group) ----------------
#define SW_WA 0
#define SW_WB 131072
#define SW_RING 196608

template <int NT>
__device__ __forceinline__ void stream_gemm(uint32_t smb,
                                            const unsigned char* __restrict__ Asrc0,
                                            uint32_t wbase, uint32_t wstride,
                                            float (*acc)[4]) {
    const int tid = threadIdx.x, lane = tid & 31, warp = tid >> 5;
    const int wm = warp >> 2, wn = warp & 3;
    const int rx = (lane & 7) << 4;
    const int colA = (lane >> 4) << 4;
    const int colB = ((lane >> 3) & 1) << 4;
    int rA[2], rB[NT / 2];
#pragma unroll
    for (int mt = 0; mt < 2; mt++)
        rA[mt] = (wm * 32 + mt * 16 + (lane & 15)) * 128;
#pragma unroll
    for (int p = 0; p < NT / 2; p++)
        rB[p] = (wn * (NT * 8) + p * 16 + (lane & 7) + ((lane >> 4) << 3)) * 128;

    auto docopy = [&](int kt) {
        const uint32_t da = smb + SW_RING + (kt & 1) * 16384;
        const unsigned char* sa = Asrc0 + (size_t)kt * ATILE;
        cpa16(da + tid * 16, sa + (size_t)tid * 16);
        cpa16(da + (tid + 512) * 16, sa + (size_t)(tid + 512) * 16);
    };

    docopy(0); cpa_commit();
#pragma unroll 1
    for (int kt = 0; kt < NKT; kt++) {
        cpa_wait0();
        __syncthreads();
        if (kt < NKT - 1) { docopy(kt + 1); cpa_commit(); }

        const uint32_t sA = smb + SW_RING + (kt & 1) * 16384;
        const uint32_t sW = smb + wbase + kt * wstride;
#pragma unroll
        for (int k16 = 0; k16 < 4; k16++) {
            uint32_t Ah[2][4];
#pragma unroll
            for (int mt = 0; mt < 2; mt++)
                ldsm4(Ah[mt], sA + rA[mt] + ((k16 * 32 + colA) ^ rx));
            uint32_t Bh[NT][2];
#pragma unroll
            for (int p = 0; p < NT / 2; p++) {
                uint32_t r4[4];
                ldsm4(r4, sW + rB[p] + ((k16 * 32 + colB) ^ rx));
                Bh[2 * p][0] = r4[0]; Bh[2 * p][1] = r4[1];
                Bh[2 * p + 1][0] = r4[2]; Bh[2 * p + 1][1] = r4[3];
            }
#pragma unroll
            for (int mt = 0; mt < 2; mt++)
#pragma unroll
                for (int nt = 0; nt < NT; nt++) mma16(acc[mt * NT + nt], Ah[mt], Bh[nt]);
        }
    }
}

__global__ __launch_bounds__(512, 1) __cluster_dims__(8, 1, 1)
void step_all(float* __restrict__ out) {
    extern __shared__ __align__(1024) unsigned char sm[];
    const uint32_t smb = smem_u32(sm);
    const int tid = threadIdx.x, lane = tid & 31, warp = tid >> 5;
    const int wm = warp >> 2, wn = warp & 3, g = lane >> 2, tg = lane & 3;
    const int bm = blockIdx.x >> 3, bn = blockIdx.x & 7;

    // full-coverage L2 prefetch of phase-A xproj lines for step t
    auto prefA = [&](int t) {
        if (tid < 256) {
            const int row = bm * 128 + (tid >> 1);
            pref_l2((const char*)g_xp16 + ((size_t)row * TT_ + t) * 3072 + bn * 256 + (tid & 1) * 128);
        }
    };
    // phase-B xproj lines for step t
    auto prefB = [&](int t) {
        if (tid < 128) {
            const int row = bm * 128 + tid;
            pref_l2((const char*)g_xp16 + ((size_t)row * TT_ + t) * 3072 + 2048 + bn * 128);
        }
    };

    // ---- resident weight load ----
    {
        const unsigned char* wg = g_Wgimg + (size_t)bn * NKT * ATILE;
#pragma unroll
        for (int i = 0; i < 16; i++)
            cpa16(smb + SW_WA + (tid + i * 512) * 16, wg + (size_t)(tid + i * 512) * 16);
        const unsigned char* wh = g_Whimg + (size_t)(bn >> 1) * NKT * ATILE + (bn & 1) * 8192;
#pragma unroll
        for (int kt = 0; kt < NKT; kt++)
            cpa16(smb + SW_WB + kt * 8192 + tid * 16, wh + (size_t)kt * ATILE + tid * 16);
        cpa_commit();
        prefA(0);
        cpa_wait0();
        __syncthreads();
    }

#pragma unroll 1
    for (int t = 0; t < TT_; t++) {
        // ===== phase A: [z|r] = h @ Wg^T =====
        {
            float acc[8][4];
#pragma unroll
            for (int i = 0; i < 8; i++)
#pragma unroll
                for (int e = 0; e < 4; e++) acc[i][e] = 0.0f;

            stream_gemm<4>(smb, g_Himg + (size_t)bm * NKT * ATILE, SW_WA, 16384, acc);

            const int cbase = bn * 128 + wn * 32;
#pragma unroll
            for (int mt = 0; mt < 2; mt++)
#pragma unroll
                for (int nt = 0; nt < 4; nt++) {
                    const int c = cbase + nt * 8 + tg * 2;
#pragma unroll
                    for (int h2 = 0; h2 < 2; h2++) {
                        const int irow = wm * 32 + mt * 16 + g + h2 * 8;
                        const int row = bm * 128 + irow;
                        float v0 = acc[mt * 4 + nt][h2 * 2 + 0];
                        float v1 = acc[mt * 4 + nt][h2 * 2 + 1];
                        const size_t xb = ((size_t)row * TT_ + t) * 1536;
                        float2 xp = unpack_h2(*(const uint32_t*)(g_xp16 + xb + c));
                        if (cbase < 512) {
                            float2 zv;
                            zv.x = sigmoidf_(v0 + xp.x);
                            zv.y = sigmoidf_(v1 + xp.y);
                            *(float2*)(g_z + (size_t)row * 512 + c) = zv;
                        } else {
                            const int c2 = c - 512;
                            float2 hv = *(const float2*)(g_h + (size_t)row * 512 + c2);
                            float u0 = sigmoidf_(v0 + xp.x) * hv.x;
                            float u1 = sigmoidf_(v1 + xp.y) * hv.y;
                            const size_t blk = ((size_t)bm * NKT + (c2 >> 6)) * ATILE;
                            const uint32_t off = swz((uint32_t)irow * 128 + (uint32_t)(c2 & 63) * 2);
                            *(uint32_t*)(g_Uimg + blk + off) = pack_hi(u0, u1);
                        }
                    }
                }
        }

        __threadfence();
        cl_arrive();
        prefB(t);                 // prefetch phase-B operands in the barrier shadow
        cl_wait();

        // ===== phase B: h_tilde = u @ Whh^T ; h update =====
        {
            float acc[4][4];
#pragma unroll
            for (int i = 0; i < 4; i++)
#pragma unroll
                for (int e = 0; e < 4; e++) acc[i][e] = 0.0f;

            stream_gemm<2>(smb, g_Uimg + (size_t)bm * NKT * ATILE, SW_WB, 8192, acc);

#pragma unroll
            for (int mt = 0; mt < 2; mt++)
#pragma unroll
                for (int nt = 0; nt < 2; nt++) {
                    const int c = bn * 64 + wn * 16 + nt * 8 + tg * 2;
#pragma unroll
                    for (int h2 = 0; h2 < 2; h2++) {
                        const int irow = wm * 32 + mt * 16 + g + h2 * 8;
                        const int row = bm * 128 + irow;
                        float v0 = acc[mt * 2 + nt][h2 * 2 + 0];
                        float v1 = acc[mt * 2 + nt][h2 * 2 + 1];
                        const size_t xb = ((size_t)row * TT_ + t) * 1536;
                        float2 xp = unpack_h2(*(const uint32_t*)(g_xp16 + xb + 1024 + c));
                        float2 zv = *(const float2*)(g_z + (size_t)row * 512 + c);
                        float2 hv = *(const float2*)(g_h + (size_t)row * 512 + c);
                        float hn0 = zv.x * hv.x + (1.0f - zv.x) * tanhf(v0 + xp.x);
                        float hn1 = zv.y * hv.y + (1.0f - zv.y) * tanhf(v1 + xp.y);
                        float2 hn; hn.x = hn0; hn.y = hn1;
                        *(float2*)(g_h + (size_t)row * 512 + c) = hn;
                        *(float2*)(out + ((size_t)row * TT_ + t) * 512 + c) = hn;
                        const size_t blk = ((size_t)bm * NKT + (c >> 6)) * ATILE;
                        const uint32_t off = swz((uint32_t)irow * 128 + (uint32_t)(c & 63) * 2);
                        *(uint32_t*)(g_Himg + blk + off) = pack_hi(hn0, hn1);
                    }
                }
        }

        __threadfence();
        cl_arrive();
        if (t < TT_ - 1) prefA(t + 1);   // prefetch next step's phase-A operands
        cl_wait();
    }
}

// ---------------- launch ----------------
extern "C" void kernel_launch(void* const* d_in, const int* in_sizes, int n_in,
                              void* d_out, int out_size) {
    const float* X   = (const float*)d_in[0];
    const float* Wzx = (const float*)d_in[1];
    const float* Wzh = (const float*)d_in[2];
    const float* Wrx = (const float*)d_in[3];
    const float* Wrh = (const float*)d_in[4];
    const float* Whx = (const float*)d_in[5];
    const float* Whh = (const float*)d_in[6];
    const float* bz  = (const float*)d_in[7];
    const float* br  = (const float*)d_in[8];
    const float* bh  = (const float*)d_in[9];
    float* out = (float*)d_out;

    const int SMEM0 = 2 * 32768;              // 65536 for gemm0
    const int SMEMS = 131072 + 65536 + 32768; // 229376 for step_all
    cudaFuncSetAttribute((const void*)gemm0_k, cudaFuncAttributeMaxDynamicSharedMemorySize, SMEM0);
    cudaFuncSetAttribute((const void*)step_all, cudaFuncAttributeMaxDynamicSharedMemorySize, SMEMS);

    prep_weights<<<1536, 256>>>(Wzx, Wzh, Wrx, Wrh, Whx, Whh, bz, br, bh);
    prep_x<<<32768, 256>>>(X);

    gemm0_k<<<dim3(12, 1024), 512, SMEM0>>>(out);

    step_all<<<128, 512, SMEMS>>>(out);
}

// round 14
// speedup vs baseline: 1.0004x; 1.0004x over previous
#include <cuda_runtime.h>
#include <cuda_fp16.h>
#include <cstdint>
#include <math.h>

#define D_  512
#define NB_ 2048
#define TT_ 64
#define MT_ (NB_*TT_)

#define ATILE 16384        // 128r x 64k fp16 hi-only, SW128
#define NKT 8

__device__ __align__(128) unsigned char g_Ximg[(size_t)1024 * NKT * ATILE];
__device__ __align__(128) unsigned char g_W1img[12 * NKT * ATILE];   // hi-only
__device__ __align__(128) unsigned char g_Wgimg[8 * NKT * ATILE];    // hi-only
__device__ __align__(128) unsigned char g_Whimg[4 * NKT * ATILE];    // hi-only
__device__ __align__(128) unsigned char g_Himg[16 * NKT * ATILE];
__device__ __align__(128) unsigned char g_Uimg[16 * NKT * ATILE];
__device__ __align__(16) __half g_xp16[(size_t)MT_ * 1536];          // fp16 xproj
__device__ __align__(16) float g_bias[1536];
__device__ __align__(16) float g_h[NB_ * D_];
__device__ __align__(16) float g_z[NB_ * D_];

// ---------------- helpers ----------------
__device__ __forceinline__ uint32_t swz(uint32_t o) { return o ^ ((o >> 3) & 0x70); }

__device__ __forceinline__ uint32_t pack_hi(float x0, float x1) {
    __half2 h = __floats2half2_rn(x0, x1);
    return *reinterpret_cast<uint32_t*>(&h);
}
__device__ __forceinline__ float2 unpack_h2(uint32_t u) {
    __half2 h = *reinterpret_cast<__half2*>(&u);
    return __half22float2(h);
}

__device__ __forceinline__ void aimg_write(unsigned char* img, int rt, int kt,
                                           int irow, int jj, float x0, float x1) {
    size_t blk = ((size_t)rt * NKT + kt) * ATILE;
    uint32_t off = swz((uint32_t)irow * 128 + (uint32_t)jj * 4);
    *(uint32_t*)(img + blk + off) = pack_hi(x0, x1);
}

__device__ __forceinline__ uint32_t smem_u32(const void* p) {
    uint32_t r;
    asm("{ .reg .u64 t; cvta.to.shared.u64 t, %1; cvt.u32.u64 %0, t; }" : "=r"(r) : "l"(p));
    return r;
}
__device__ __forceinline__ void cpa16(uint32_t dst, const void* src) {
    asm volatile("cp.async.cg.shared.global [%0], [%1], 16;" :: "r"(dst), "l"(src));
}
__device__ __forceinline__ void cpa_commit() { asm volatile("cp.async.commit_group;" ::: "memory"); }
__device__ __forceinline__ void cpa_wait0() { asm volatile("cp.async.wait_group 0;" ::: "memory"); }
__device__ __forceinline__ void pref_l2(const void* p) {
    asm volatile("prefetch.global.L2 [%0];" :: "l"(p));
}
__device__ __forceinline__ void cl_arrive() { asm volatile("barrier.cluster.arrive.aligned;" ::: "memory"); }
__device__ __forceinline__ void cl_wait()   { asm volatile("barrier.cluster.wait.aligned;" ::: "memory"); }

__device__ __forceinline__ void ldsm4(uint32_t* r, uint32_t addr) {
    asm volatile("ldmatrix.sync.aligned.m8n8.x4.shared.b16 {%0,%1,%2,%3}, [%4];"
                 : "=r"(r[0]), "=r"(r[1]), "=r"(r[2]), "=r"(r[3]) : "r"(addr));
}
__device__ __forceinline__ void mma16(float* d, const uint32_t* a, const uint32_t* b) {
    asm volatile(
        "mma.sync.aligned.m16n8k16.row.col.f32.f16.f16.f32 "
        "{%0,%1,%2,%3},{%4,%5,%6,%7},{%8,%9},{%0,%1,%2,%3};"
        : "+f"(d[0]), "+f"(d[1]), "+f"(d[2]), "+f"(d[3])
        : "r"(a[0]), "r"(a[1]), "r"(a[2]), "r"(a[3]), "r"(b[0]), "r"(b[1]));
}
__device__ __forceinline__ float sigmoidf_(float x) { return 1.0f / (1.0f + expf(-x)); }

// ---------------- prep ----------------
__global__ void prep_weights(const float* __restrict__ Wzx, const float* __restrict__ Wzh,
                             const float* __restrict__ Wrx, const float* __restrict__ Wrh,
                             const float* __restrict__ Whx, const float* __restrict__ Whh,
                             const float* __restrict__ bz, const float* __restrict__ br,
                             const float* __restrict__ bh) {
    int i = blockIdx.x * 256 + threadIdx.x;
    int n = i >> 8, jp = i & 255;
    int kt = jp >> 5, jj = jp & 31, k = jp * 2;
    {
        const float* s = (n < 512) ? Wzx : (n < 1024 ? Wrx : Whx);
        int nn = (n < 512) ? n : (n < 1024 ? n - 512 : n - 1024);
        aimg_write(g_W1img, n >> 7, kt, n & 127, jj, s[nn * 512 + k], s[nn * 512 + k + 1]);
    }
    if (n < 1024) {
        const float* s = (n < 512) ? Wzh : Wrh;
        int nn = n & 511;
        aimg_write(g_Wgimg, n >> 7, kt, n & 127, jj, s[nn * 512 + k], s[nn * 512 + k + 1]);
    }
    if (n < 512)
        aimg_write(g_Whimg, n >> 7, kt, n & 127, jj, Whh[n * 512 + k], Whh[n * 512 + k + 1]);
    if (i < 1536) g_bias[i] = (i < 512) ? bz[i] : (i < 1024 ? br[i - 512] : bh[i - 1024]);
    if (i < NB_ * D_ / 4) ((float4*)g_h)[i] = make_float4(0.f, 0.f, 0.f, 0.f);
    if (i < 16 * NKT * ATILE / 16) ((uint4*)g_Himg)[i] = make_uint4(0, 0, 0, 0);
}

__global__ void prep_x(const float* __restrict__ X) {
    int i = blockIdx.x * 256 + threadIdx.x;      // 32768 blocks; 8 cols per thread
    int row = i >> 6, jq = i & 63;
    const float* src = X + (size_t)row * 512 + jq * 8;
    float4 a = *(const float4*)src, b = *(const float4*)(src + 4);
    uint4 v = make_uint4(pack_hi(a.x, a.y), pack_hi(a.z, a.w),
                         pack_hi(b.x, b.y), pack_hi(b.z, b.w));
    int kt = jq >> 3;
    size_t blk = ((size_t)(row >> 7) * NKT + kt) * ATILE;
    uint32_t off = swz((uint32_t)(row & 127) * 128 + (uint32_t)(jq & 7) * 16);
    *(uint4*)(g_Ximg + blk + off) = v;
}

// ---------------- gemm0 core ----------
__device__ __forceinline__ void gemm0_core(uint32_t smb,
                                           const unsigned char* __restrict__ Asrc0,
                                           const unsigned char* __restrict__ Bsrc0,
                                           float (*acc)[4]) {
    constexpr int SBUF = 32768;
    const int tid = threadIdx.x, lane = tid & 31, warp = tid >> 5;
    const int wm = warp >> 2, wn = warp & 3;
    const int rx = (lane & 7) << 4;
    const int colA = (lane >> 4) << 4;
    const int colB = ((lane >> 3) & 1) << 4;
    int rA[2], rB[2];
#pragma unroll
    for (int mt = 0; mt < 2; mt++)
        rA[mt] = (wm * 32 + mt * 16 + (lane & 15)) * 128;
#pragma unroll
    for (int p = 0; p < 2; p++)
        rB[p] = (wn * 32 + p * 16 + (lane & 7) + ((lane >> 4) << 3)) * 128;

    auto docopy = [&](int kt) {
        const uint32_t da = smb + (kt & 1) * SBUF;
        const unsigned char* sa = Asrc0 + (size_t)kt * ATILE;
        cpa16(da + tid * 16, sa + (size_t)tid * 16);
        cpa16(da + (tid + 512) * 16, sa + (size_t)(tid + 512) * 16);
        const uint32_t db = da + 16384;
        const unsigned char* sb = Bsrc0 + (size_t)kt * ATILE;
        cpa16(db + tid * 16, sb + (size_t)tid * 16);
        cpa16(db + (tid + 512) * 16, sb + (size_t)(tid + 512) * 16);
    };

    docopy(0); cpa_commit();
#pragma unroll 1
    for (int kt = 0; kt < NKT; kt++) {
        cpa_wait0();
        __syncthreads();
        if (kt < NKT - 1) { docopy(kt + 1); cpa_commit(); }

        const uint32_t sA = smb + (kt & 1) * SBUF;
        const uint32_t sB = sA + 16384;
#pragma unroll
        for (int k16 = 0; k16 < 4; k16++) {
            uint32_t Ah[2][4];
#pragma unroll
            for (int mt = 0; mt < 2; mt++)
                ldsm4(Ah[mt], sA + rA[mt] + ((k16 * 32 + colA) ^ rx));
            uint32_t Bh[4][2];
#pragma unroll
            for (int p = 0; p < 2; p++) {
                uint32_t r4[4];
                ldsm4(r4, sB + rB[p] + ((k16 * 32 + colB) ^ rx));
                Bh[2 * p][0] = r4[0]; Bh[2 * p][1] = r4[1];
                Bh[2 * p + 1][0] = r4[2]; Bh[2 * p + 1][1] = r4[3];
            }
#pragma unroll
            for (int mt = 0; mt < 2; mt++)
#pragma unroll
                for (int nt = 0; nt < 4; nt++) mma16(acc[mt * 4 + nt], Ah[mt], Bh[nt]);
        }
    }
}

// ---------------- phase-1 kernel ----------------
__global__ __launch_bounds__(512, 1) void gemm0_k(float* __restrict__ out) {
    extern __shared__ __align__(1024) unsigned char sm[];
    const uint32_t smb = smem_u32(sm);
    const int tid = threadIdx.x, lane = tid & 31, warp = tid >> 5;
    const int wm = warp >> 2, wn = warp & 3, g = lane >> 2, tg = lane & 3;
    const int bn = blockIdx.x, bm = blockIdx.y;

    float acc[8][4];
#pragma unroll
    for (int i = 0; i < 8; i++)
#pragma unroll
        for (int e = 0; e < 4; e++) acc[i][e] = 0.0f;

    gemm0_core(smb, g_Ximg + (size_t)bm * NKT * ATILE,
               g_W1img + (size_t)bn * NKT * ATILE, acc);

    const int cbase = bn * 128 + wn * 32;
#pragma unroll
    for (int mt = 0; mt < 2; mt++)
#pragma unroll
        for (int nt = 0; nt < 4; nt++) {
            const int c = cbase + nt * 8 + tg * 2;
            float2 b = *(const float2*)(g_bias + c);
#pragma unroll
            for (int h2 = 0; h2 < 2; h2++) {
                const int row = bm * 128 + wm * 32 + mt * 16 + g + h2 * 8;
                float o0 = acc[mt * 4 + nt][h2 * 2 + 0] + b.x;
                float o1 = acc[mt * 4 + nt][h2 * 2 + 1] + b.y;
                *(uint32_t*)(g_xp16 + (size_t)row * 1536 + c) = pack_hi(o0, o1);
            }
        }
}

// ---------------- persistent recurrence (cluster = 8-CTA group) ----------------
#define SW_WA 0
#define SW_WB 131072
#define SW_RING 196608

template <int NT>
__device__ __forceinline__ void stream_gemm(uint32_t smb,
                                            const unsigned char* __restrict__ Asrc0,
                                            uint32_t wbase, uint32_t wstride,
                                            float (*acc)[4]) {
    const int tid = threadIdx.x, lane = tid & 31, warp = tid >> 5;
    const int wm = warp >> 2, wn = warp & 3;
    const int rx = (lane & 7) << 4;
    const int colA = (lane >> 4) << 4;
    const int colB = ((lane >> 3) & 1) << 4;
    int rA[2], rB[NT / 2];
#pragma unroll
    for (int mt = 0; mt < 2; mt++)
        rA[mt] = (wm * 32 + mt * 16 + (lane & 15)) * 128;
#pragma unroll
    for (int p = 0; p < NT / 2; p++)
        rB[p] = (wn * (NT * 8) + p * 16 + (lane & 7) + ((lane >> 4) << 3)) * 128;

    auto docopy = [&](int kt) {
        const uint32_t da = smb + SW_RING + (kt & 1) * 16384;
        const unsigned char* sa = Asrc0 + (size_t)kt * ATILE;
        cpa16(da + tid * 16, sa + (size_t)tid * 16);
        cpa16(da + (tid + 512) * 16, sa + (size_t)(tid + 512) * 16);
    };

    docopy(0); cpa_commit();
#pragma unroll 1
    for (int kt = 0; kt < NKT; kt++) {
        cpa_wait0();
        __syncthreads();
        if (kt < NKT - 1) { docopy(kt + 1); cpa_commit(); }

        const uint32_t sA = smb + SW_RING + (kt & 1) * 16384;
        const uint32_t sW = smb + wbase + kt * wstride;
#pragma unroll
        for (int k16 = 0; k16 < 4; k16++) {
            uint32_t Ah[2][4];
#pragma unroll
            for (int mt = 0; mt < 2; mt++)
                ldsm4(Ah[mt], sA + rA[mt] + ((k16 * 32 + colA) ^ rx));
            uint32_t Bh[NT][2];
#pragma unroll
            for (int p = 0; p < NT / 2; p++) {
                uint32_t r4[4];
                ldsm4(r4, sW + rB[p] + ((k16 * 32 + colB) ^ rx));
                Bh[2 * p][0] = r4[0]; Bh[2 * p][1] = r4[1];
                Bh[2 * p + 1][0] = r4[2]; Bh[2 * p + 1][1] = r4[3];
            }
#pragma unroll
            for (int mt = 0; mt < 2; mt++)
#pragma unroll
                for (int nt = 0; nt < NT; nt++) mma16(acc[mt * NT + nt], Ah[mt], Bh[nt]);
        }
    }
}

__global__ __launch_bounds__(512, 1) __cluster_dims__(8, 1, 1)
void step_all(float* __restrict__ out) {
    extern __shared__ __align__(1024) unsigned char sm[];
    const uint32_t smb = smem_u32(sm);
    const int tid = threadIdx.x, lane = tid & 31, warp = tid >> 5;
    const int wm = warp >> 2, wn = warp & 3, g = lane >> 2, tg = lane & 3;
    const int bm = blockIdx.x >> 3, bn = blockIdx.x & 7;

    // full-coverage L2 prefetch of phase-A xproj lines for step t
    auto prefA = [&](int t) {
        if (tid < 256) {
            const int row = bm * 128 + (tid >> 1);
            pref_l2((const char*)g_xp16 + ((size_t)row * TT_ + t) * 3072 + bn * 256 + (tid & 1) * 128);
        }
    };
    // phase-B xproj lines for step t
    auto prefB = [&](int t) {
        if (tid < 128) {
            const int row = bm * 128 + tid;
            pref_l2((const char*)g_xp16 + ((size_t)row * TT_ + t) * 3072 + 2048 + bn * 128);
        }
    };

    // ---- resident weight load ----
    {
        const unsigned char* wg = g_Wgimg + (size_t)bn * NKT * ATILE;
#pragma unroll
        for (int i = 0; i < 16; i++)
            cpa16(smb + SW_WA + (tid + i * 512) * 16, wg + (size_t)(tid + i * 512) * 16);
        const unsigned char* wh = g_Whimg + (size_t)(bn >> 1) * NKT * ATILE + (bn & 1) * 8192;
#pragma unroll
        for (int kt = 0; kt < NKT; kt++)
            cpa16(smb + SW_WB + kt * 8192 + tid * 16, wh + (size_t)kt * ATILE + tid * 16);
        cpa_commit();
        prefA(0);
        cpa_wait0();
        __syncthreads();
    }

#pragma unroll 1
    for (int t = 0; t < TT_; t++) {
        // ===== phase A: [z|r] = h @ Wg^T =====
        {
            float acc[8][4];
#pragma unroll
            for (int i = 0; i < 8; i++)
#pragma unroll
                for (int e = 0; e < 4; e++) acc[i][e] = 0.0f;

            stream_gemm<4>(smb, g_Himg + (size_t)bm * NKT * ATILE, SW_WA, 16384, acc);

            const int cbase = bn * 128 + wn * 32;
#pragma unroll
            for (int mt = 0; mt < 2; mt++)
#pragma unroll
                for (int nt = 0; nt < 4; nt++) {
                    const int c = cbase + nt * 8 + tg * 2;
#pragma unroll
                    for (int h2 = 0; h2 < 2; h2++) {
                        const int irow = wm * 32 + mt * 16 + g + h2 * 8;
                        const int row = bm * 128 + irow;
                        float v0 = acc[mt * 4 + nt][h2 * 2 + 0];
                        float v1 = acc[mt * 4 + nt][h2 * 2 + 1];
                        const size_t xb = ((size_t)row * TT_ + t) * 1536;
                        float2 xp = unpack_h2(*(const uint32_t*)(g_xp16 + xb + c));
                        if (cbase < 512) {
                            float2 zv;
                            zv.x = sigmoidf_(v0 + xp.x);
                            zv.y = sigmoidf_(v1 + xp.y);
                            *(float2*)(g_z + (size_t)row * 512 + c) = zv;
                        } else {
                            const int c2 = c - 512;
                            float2 hv = *(const float2*)(g_h + (size_t)row * 512 + c2);
                            float u0 = sigmoidf_(v0 + xp.x) * hv.x;
                            float u1 = sigmoidf_(v1 + xp.y) * hv.y;
                            const size_t blk = ((size_t)bm * NKT + (c2 >> 6)) * ATILE;
                            const uint32_t off = swz((uint32_t)irow * 128 + (uint32_t)(c2 & 63) * 2);
                            *(uint32_t*)(g_Uimg + blk + off) = pack_hi(u0, u1);
                        }
                    }
                }
        }

        __threadfence();
        cl_arrive();
        prefB(t);                 // prefetch phase-B operands in the barrier shadow
        cl_wait();

        // ===== phase B: h_tilde = u @ Whh^T ; h update =====
        {
            float acc[4][4];
#pragma unroll
            for (int i = 0; i < 4; i++)
#pragma unroll
                for (int e = 0; e < 4; e++) acc[i][e] = 0.0f;

            stream_gemm<2>(smb, g_Uimg + (size_t)bm * NKT * ATILE, SW_WB, 8192, acc);

#pragma unroll
            for (int mt = 0; mt < 2; mt++)
#pragma unroll
                for (int nt = 0; nt < 2; nt++) {
                    const int c = bn * 64 + wn * 16 + nt * 8 + tg * 2;
#pragma unroll
                    for (int h2 = 0; h2 < 2; h2++) {
                        const int irow = wm * 32 + mt * 16 + g + h2 * 8;
                        const int row = bm * 128 + irow;
                        float v0 = acc[mt * 2 + nt][h2 * 2 + 0];
                        float v1 = acc[mt * 2 + nt][h2 * 2 + 1];
                        const size_t xb = ((size_t)row * TT_ + t) * 1536;
                        float2 xp = unpack_h2(*(const uint32_t*)(g_xp16 + xb + 1024 + c));
                        float2 zv = *(const float2*)(g_z + (size_t)row * 512 + c);
                        float2 hv = *(const float2*)(g_h + (size_t)row * 512 + c);
                        float hn0 = zv.x * hv.x + (1.0f - zv.x) * tanhf(v0 + xp.x);
                        float hn1 = zv.y * hv.y + (1.0f - zv.y) * tanhf(v1 + xp.y);
                        float2 hn; hn.x = hn0; hn.y = hn1;
                        *(float2*)(g_h + (size_t)row * 512 + c) = hn;
                        *(float2*)(out + ((size_t)row * TT_ + t) * 512 + c) = hn;
                        const size_t blk = ((size_t)bm * NKT + (c >> 6)) * ATILE;
                        const uint32_t off = swz((uint32_t)irow * 128 + (uint32_t)(c & 63) * 2);
                        *(uint32_t*)(g_Himg + blk + off) = pack_hi(hn0, hn1);
                    }
                }
        }

        __threadfence();
        cl_arrive();
        if (t < TT_ - 1) prefA(t + 1);   // prefetch next step's phase-A operands
        cl_wait();
    }
}

// ---------------- launch ----------------
extern "C" void kernel_launch(void* const* d_in, const int* in_sizes, int n_in,
                              void* d_out, int out_size) {
    const float* X   = (const float*)d_in[0];
    const float* Wzx = (const float*)d_in[1];
    const float* Wzh = (const float*)d_in[2];
    const float* Wrx = (const float*)d_in[3];
    const float* Wrh = (const float*)d_in[4];
    const float* Whx = (const float*)d_in[5];
    const float* Whh = (const float*)d_in[6];
    const float* bz  = (const float*)d_in[7];
    const float* br  = (const float*)d_in[8];
    const float* bh  = (const float*)d_in[9];
    float* out = (float*)d_out;

    const int SMEM0 = 2 * 32768;              // 65536 for gemm0
    const int SMEMS = 131072 + 65536 + 32768; // 229376 for step_all
    cudaFuncSetAttribute((const void*)gemm0_k, cudaFuncAttributeMaxDynamicSharedMemorySize, SMEM0);
    cudaFuncSetAttribute((const void*)step_all, cudaFuncAttributeMaxDynamicSharedMemorySize, SMEMS);

    prep_weights<<<1536, 256>>>(Wzx, Wzh, Wrx, Wrh, Whx, Whh, bz, br, bh);
    prep_x<<<32768, 256>>>(X);

    gemm0_k<<<dim3(12, 1024), 512, SMEM0>>>(out);

    step_all<<<128, 512, SMEMS>>>(out);
}

// round 15
// speedup vs baseline: 1.5328x; 1.5322x over previous
#include <cuda_runtime.h>
#include <cuda_fp16.h>
#include <cstdint>
#include <math.h>

#define D_  512
#define NB_ 2048
#define TT_ 64
#define MT_ (NB_*TT_)

#define ATILE 16384        // 128r x 64k fp16 hi-only, SW128
#define NKT 8

__device__ __align__(128) unsigned char g_Ximg[(size_t)1024 * NKT * ATILE];
__device__ __align__(128) unsigned char g_W1img[12 * NKT * ATILE];   // hi-only
__device__ __align__(128) unsigned char g_Wgimg[8 * NKT * ATILE];    // hi-only
__device__ __align__(128) unsigned char g_Whimg[4 * NKT * ATILE];    // hi-only
__device__ __align__(128) unsigned char g_Himg[16 * NKT * ATILE];
__device__ __align__(128) unsigned char g_Uimg[16 * NKT * ATILE];
__device__ __align__(16) __half g_xp16[(size_t)MT_ * 1536];          // fp16 xproj
__device__ __align__(16) float g_bias[1536];
__device__ __align__(16) float g_h[NB_ * D_];
__device__ __align__(16) float g_z[NB_ * D_];
__device__ __align__(128) unsigned g_gc[16 * 32];
__device__ __align__(128) unsigned g_gf[16 * 32];

// ---------------- helpers ----------------
__device__ __forceinline__ uint32_t swz(uint32_t o) { return o ^ ((o >> 3) & 0x70); }

__device__ __forceinline__ uint32_t pack_hi(float x0, float x1) {
    __half2 h = __floats2half2_rn(x0, x1);
    return *reinterpret_cast<uint32_t*>(&h);
}
__device__ __forceinline__ float2 unpack_h2(uint32_t u) {
    __half2 h = *reinterpret_cast<__half2*>(&u);
    return __half22float2(h);
}

__device__ __forceinline__ void aimg_write(unsigned char* img, int rt, int kt,
                                           int irow, int jj, float x0, float x1) {
    size_t blk = ((size_t)rt * NKT + kt) * ATILE;
    uint32_t off = swz((uint32_t)irow * 128 + (uint32_t)jj * 4);
    *(uint32_t*)(img + blk + off) = pack_hi(x0, x1);
}

__device__ __forceinline__ uint32_t smem_u32(const void* p) {
    uint32_t r;
    asm("{ .reg .u64 t; cvta.to.shared.u64 t, %1; cvt.u32.u64 %0, t; }" : "=r"(r) : "l"(p));
    return r;
}
__device__ __forceinline__ void cpa16(uint32_t dst, const void* src) {
    asm volatile("cp.async.cg.shared.global [%0], [%1], 16;" :: "r"(dst), "l"(src));
}
__device__ __forceinline__ void cpa_commit() { asm volatile("cp.async.commit_group;" ::: "memory"); }
__device__ __forceinline__ void cpa_wait0() { asm volatile("cp.async.wait_group 0;" ::: "memory"); }
__device__ __forceinline__ void pref_l2(const void* p) {
    asm volatile("prefetch.global.L2 [%0];" :: "l"(p));
}

__device__ __forceinline__ void ldsm4(uint32_t* r, uint32_t addr) {
    asm volatile("ldmatrix.sync.aligned.m8n8.x4.shared.b16 {%0,%1,%2,%3}, [%4];"
                 : "=r"(r[0]), "=r"(r[1]), "=r"(r[2]), "=r"(r[3]) : "r"(addr));
}
__device__ __forceinline__ void mma16(float* d, const uint32_t* a, const uint32_t* b) {
    asm volatile(
        "mma.sync.aligned.m16n8k16.row.col.f32.f16.f16.f32 "
        "{%0,%1,%2,%3},{%4,%5,%6,%7},{%8,%9},{%0,%1,%2,%3};"
        : "+f"(d[0]), "+f"(d[1]), "+f"(d[2]), "+f"(d[3])
        : "r"(a[0]), "r"(a[1]), "r"(a[2]), "r"(a[3]), "r"(b[0]), "r"(b[1]));
}
__device__ __forceinline__ float sigmoidf_(float x) { return 1.0f / (1.0f + expf(-x)); }

// ---------------- prep ----------------
__global__ void prep_weights(const float* __restrict__ Wzx, const float* __restrict__ Wzh,
                             const float* __restrict__ Wrx, const float* __restrict__ Wrh,
                             const float* __restrict__ Whx, const float* __restrict__ Whh,
                             const float* __restrict__ bz, const float* __restrict__ br,
                             const float* __restrict__ bh) {
    int i = blockIdx.x * 256 + threadIdx.x;
    int n = i >> 8, jp = i & 255;
    int kt = jp >> 5, jj = jp & 31, k = jp * 2;
    {
        const float* s = (n < 512) ? Wzx : (n < 1024 ? Wrx : Whx);
        int nn = (n < 512) ? n : (n < 1024 ? n - 512 : n - 1024);
        aimg_write(g_W1img, n >> 7, kt, n & 127, jj, s[nn * 512 + k], s[nn * 512 + k + 1]);
    }
    if (n < 1024) {
        const float* s = (n < 512) ? Wzh : Wrh;
        int nn = n & 511;
        aimg_write(g_Wgimg, n >> 7, kt, n & 127, jj, s[nn * 512 + k], s[nn * 512 + k + 1]);
    }
    if (n < 512)
        aimg_write(g_Whimg, n >> 7, kt, n & 127, jj, Whh[n * 512 + k], Whh[n * 512 + k + 1]);
    if (i < 1536) g_bias[i] = (i < 512) ? bz[i] : (i < 1024 ? br[i - 512] : bh[i - 1024]);
    if (i < NB_ * D_ / 4) ((float4*)g_h)[i] = make_float4(0.f, 0.f, 0.f, 0.f);
    if (i < 16 * NKT * ATILE / 16) ((uint4*)g_Himg)[i] = make_uint4(0, 0, 0, 0);
}

__global__ void prep_x(const float* __restrict__ X) {
    int i = blockIdx.x * 256 + threadIdx.x;      // 32768 blocks; 8 cols per thread
    int row = i >> 6, jq = i & 63;
    const float* src = X + (size_t)row * 512 + jq * 8;
    float4 a = *(const float4*)src, b = *(const float4*)(src + 4);
    uint4 v = make_uint4(pack_hi(a.x, a.y), pack_hi(a.z, a.w),
                         pack_hi(b.x, b.y), pack_hi(b.z, b.w));
    int kt = jq >> 3;
    size_t blk = ((size_t)(row >> 7) * NKT + kt) * ATILE;
    uint32_t off = swz((uint32_t)(row & 127) * 128 + (uint32_t)(jq & 7) * 16);
    *(uint4*)(g_Ximg + blk + off) = v;
}

// ---------------- gemm0 core ----------
__device__ __forceinline__ void gemm0_core(uint32_t smb,
                                           const unsigned char* __restrict__ Asrc0,
                                           const unsigned char* __restrict__ Bsrc0,
                                           float (*acc)[4]) {
    constexpr int SBUF = 32768;
    const int tid = threadIdx.x, lane = tid & 31, warp = tid >> 5;
    const int wm = warp >> 2, wn = warp & 3;
    const int rx = (lane & 7) << 4;
    const int colA = (lane >> 4) << 4;
    const int colB = ((lane >> 3) & 1) << 4;
    int rA[2], rB[2];
#pragma unroll
    for (int mt = 0; mt < 2; mt++)
        rA[mt] = (wm * 32 + mt * 16 + (lane & 15)) * 128;
#pragma unroll
    for (int p = 0; p < 2; p++)
        rB[p] = (wn * 32 + p * 16 + (lane & 7) + ((lane >> 4) << 3)) * 128;

    auto docopy = [&](int kt) {
        const uint32_t da = smb + (kt & 1) * SBUF;
        const unsigned char* sa = Asrc0 + (size_t)kt * ATILE;
        cpa16(da + tid * 16, sa + (size_t)tid * 16);
        cpa16(da + (tid + 512) * 16, sa + (size_t)(tid + 512) * 16);
        const uint32_t db = da + 16384;
        const unsigned char* sb = Bsrc0 + (size_t)kt * ATILE;
        cpa16(db + tid * 16, sb + (size_t)tid * 16);
        cpa16(db + (tid + 512) * 16, sb + (size_t)(tid + 512) * 16);
    };

    docopy(0); cpa_commit();
#pragma unroll 1
    for (int kt = 0; kt < NKT; kt++) {
        cpa_wait0();
        __syncthreads();
        if (kt < NKT - 1) { docopy(kt + 1); cpa_commit(); }

        const uint32_t sA = smb + (kt & 1) * SBUF;
        const uint32_t sB = sA + 16384;
#pragma unroll
        for (int k16 = 0; k16 < 4; k16++) {
            uint32_t Ah[2][4];
#pragma unroll
            for (int mt = 0; mt < 2; mt++)
                ldsm4(Ah[mt], sA + rA[mt] + ((k16 * 32 + colA) ^ rx));
            uint32_t Bh[4][2];
#pragma unroll
            for (int p = 0; p < 2; p++) {
                uint32_t r4[4];
                ldsm4(r4, sB + rB[p] + ((k16 * 32 + colB) ^ rx));
                Bh[2 * p][0] = r4[0]; Bh[2 * p][1] = r4[1];
                Bh[2 * p + 1][0] = r4[2]; Bh[2 * p + 1][1] = r4[3];
            }
#pragma unroll
            for (int mt = 0; mt < 2; mt++)
#pragma unroll
                for (int nt = 0; nt < 4; nt++) mma16(acc[mt * 4 + nt], Ah[mt], Bh[nt]);
        }
    }
}

// ---------------- phase-1 kernel ----------------
__global__ __launch_bounds__(512, 1) void gemm0_k(float* __restrict__ out) {
    extern __shared__ __align__(1024) unsigned char sm[];
    const uint32_t smb = smem_u32(sm);
    const int tid = threadIdx.x, lane = tid & 31, warp = tid >> 5;
    const int wm = warp >> 2, wn = warp & 3, g = lane >> 2, tg = lane & 3;
    const int bn = blockIdx.x, bm = blockIdx.y;

    float acc[8][4];
#pragma unroll
    for (int i = 0; i < 8; i++)
#pragma unroll
        for (int e = 0; e < 4; e++) acc[i][e] = 0.0f;

    gemm0_core(smb, g_Ximg + (size_t)bm * NKT * ATILE,
               g_W1img + (size_t)bn * NKT * ATILE, acc);

    const int cbase = bn * 128 + wn * 32;
#pragma unroll
    for (int mt = 0; mt < 2; mt++)
#pragma unroll
        for (int nt = 0; nt < 4; nt++) {
            const int c = cbase + nt * 8 + tg * 2;
            float2 b = *(const float2*)(g_bias + c);
#pragma unroll
            for (int h2 = 0; h2 < 2; h2++) {
                const int row = bm * 128 + wm * 32 + mt * 16 + g + h2 * 8;
                float o0 = acc[mt * 4 + nt][h2 * 2 + 0] + b.x;
                float o1 = acc[mt * 4 + nt][h2 * 2 + 1] + b.y;
                *(uint32_t*)(g_xp16 + (size_t)row * 1536 + c) = pack_hi(o0, o1);
            }
        }
}

// ---------------- per-group (8-CTA) atomic barrier ----------------
__device__ __forceinline__ void group_bar(int gid) {
    __threadfence();
    __syncthreads();
    if (threadIdx.x == 0) {
        unsigned entry = *(volatile unsigned*)&g_gf[gid * 32];
        unsigned tk = atomicAdd(&g_gc[gid * 32], 1);
        if (tk == 7) {
            g_gc[gid * 32] = 0;
            __threadfence();
            atomicAdd(&g_gf[gid * 32], 1);
        } else {
            while (*(volatile unsigned*)&g_gf[gid * 32] == entry) { }
        }
        __threadfence();
    }
    __syncthreads();
}

// ---------------- persistent recurrence ----------------
#define SW_WA 0
#define SW_WB 131072
#define SW_RING 196608

template <int NT>
__device__ __forceinline__ void stream_gemm(uint32_t smb,
                                            const unsigned char* __restrict__ Asrc0,
                                            uint32_t wbase, uint32_t wstride,
                                            float (*acc)[4]) {
    const int tid = threadIdx.x, lane = tid & 31, warp = tid >> 5;
    const int wm = warp >> 2, wn = warp & 3;
    const int rx = (lane & 7) << 4;
    const int colA = (lane >> 4) << 4;
    const int colB = ((lane >> 3) & 1) << 4;
    int rA[2], rB[NT / 2];
#pragma unroll
    for (int mt = 0; mt < 2; mt++)
        rA[mt] = (wm * 32 + mt * 16 + (lane & 15)) * 128;
#pragma unroll
    for (int p = 0; p < NT / 2; p++)
        rB[p] = (wn * (NT * 8) + p * 16 + (lane & 7) + ((lane >> 4) << 3)) * 128;

    auto docopy = [&](int kt) {
        const uint32_t da = smb + SW_RING + (kt & 1) * 16384;
        const unsigned char* sa = Asrc0 + (size_t)kt * ATILE;
        cpa16(da + tid * 16, sa + (size_t)tid * 16);
        cpa16(da + (tid + 512) * 16, sa + (size_t)(tid + 512) * 16);
    };

    docopy(0); cpa_commit();
#pragma unroll 1
    for (int kt = 0; kt < NKT; kt++) {
        cpa_wait0();
        __syncthreads();
        if (kt < NKT - 1) { docopy(kt + 1); cpa_commit(); }

        const uint32_t sA = smb + SW_RING + (kt & 1) * 16384;
        const uint32_t sW = smb + wbase + kt * wstride;
#pragma unroll
        for (int k16 = 0; k16 < 4; k16++) {
            uint32_t Ah[2][4];
#pragma unroll
            for (int mt = 0; mt < 2; mt++)
                ldsm4(Ah[mt], sA + rA[mt] + ((k16 * 32 + colA) ^ rx));
            uint32_t Bh[NT][2];
#pragma unroll
            for (int p = 0; p < NT / 2; p++) {
                uint32_t r4[4];
                ldsm4(r4, sW + rB[p] + ((k16 * 32 + colB) ^ rx));
                Bh[2 * p][0] = r4[0]; Bh[2 * p][1] = r4[1];
                Bh[2 * p + 1][0] = r4[2]; Bh[2 * p + 1][1] = r4[3];
            }
#pragma unroll
            for (int mt = 0; mt < 2; mt++)
#pragma unroll
                for (int nt = 0; nt < NT; nt++) mma16(acc[mt * NT + nt], Ah[mt], Bh[nt]);
        }
    }
}

__global__ __launch_bounds__(512, 1) void step_all(float* __restrict__ out) {
    extern __shared__ __align__(1024) unsigned char sm[];
    const uint32_t smb = smem_u32(sm);
    const int tid = threadIdx.x, lane = tid & 31, warp = tid >> 5;
    const int wm = warp >> 2, wn = warp & 3, g = lane >> 2, tg = lane & 3;
    const int bm = blockIdx.x >> 3, bn = blockIdx.x & 7;

    // full-coverage L2 prefetch of phase-A xproj lines (256 x 128B = this CTA's slice)
    auto prefA = [&](int t) {
        if (tid < 256) {
            const int row = bm * 128 + (tid >> 1);
            pref_l2((const char*)g_xp16 + ((size_t)row * TT_ + t) * 3072 + bn * 256 + (tid & 1) * 128);
        }
    };
    // phase-B xproj lines (128 x 128B)
    auto prefB = [&](int t) {
        if (tid < 128) {
            const int row = bm * 128 + tid;
            pref_l2((const char*)g_xp16 + ((size_t)row * TT_ + t) * 3072 + 2048 + bn * 128);
        }
    };

    // ---- resident weight load ----
    {
        const unsigned char* wg = g_Wgimg + (size_t)bn * NKT * ATILE;
#pragma unroll
        for (int i = 0; i < 16; i++)
            cpa16(smb + SW_WA + (tid + i * 512) * 16, wg + (size_t)(tid + i * 512) * 16);
        const unsigned char* wh = g_Whimg + (size_t)(bn >> 1) * NKT * ATILE + (bn & 1) * 8192;
#pragma unroll
        for (int kt = 0; kt < NKT; kt++)
            cpa16(smb + SW_WB + kt * 8192 + tid * 16, wh + (size_t)kt * ATILE + tid * 16);
        cpa_commit();
        prefA(0);
        cpa_wait0();
        __syncthreads();
    }

#pragma unroll 1
    for (int t = 0; t < TT_; t++) {
        // ===== phase A: [z|r] = h @ Wg^T =====
        {
            float acc[8][4];
#pragma unroll
            for (int i = 0; i < 8; i++)
#pragma unroll
                for (int e = 0; e < 4; e++) acc[i][e] = 0.0f;

            stream_gemm<4>(smb, g_Himg + (size_t)bm * NKT * ATILE, SW_WA, 16384, acc);

            const int cbase = bn * 128 + wn * 32;
#pragma unroll
            for (int mt = 0; mt < 2; mt++)
#pragma unroll
                for (int nt = 0; nt < 4; nt++) {
                    const int c = cbase + nt * 8 + tg * 2;
#pragma unroll
                    for (int h2 = 0; h2 < 2; h2++) {
                        const int irow = wm * 32 + mt * 16 + g + h2 * 8;
                        const int row = bm * 128 + irow;
                        float v0 = acc[mt * 4 + nt][h2 * 2 + 0];
                        float v1 = acc[mt * 4 + nt][h2 * 2 + 1];
                        const size_t xb = ((size_t)row * TT_ + t) * 1536;
                        float2 xp = unpack_h2(*(const uint32_t*)(g_xp16 + xb + c));
                        if (cbase < 512) {
                            float2 zv;
                            zv.x = sigmoidf_(v0 + xp.x);
                            zv.y = sigmoidf_(v1 + xp.y);
                            *(float2*)(g_z + (size_t)row * 512 + c) = zv;
                        } else {
                            const int c2 = c - 512;
                            float2 hv = *(const float2*)(g_h + (size_t)row * 512 + c2);
                            float u0 = sigmoidf_(v0 + xp.x) * hv.x;
                            float u1 = sigmoidf_(v1 + xp.y) * hv.y;
                            const size_t blk = ((size_t)bm * NKT + (c2 >> 6)) * ATILE;
                            const uint32_t off = swz((uint32_t)irow * 128 + (uint32_t)(c2 & 63) * 2);
                            *(uint32_t*)(g_Uimg + blk + off) = pack_hi(u0, u1);
                        }
                    }
                }
        }

        prefB(t);          // prefetch phase-B operands; flight time overlaps barrier
        group_bar(bm);

        // ===== phase B: h_tilde = u @ Whh^T ; h update =====
        {
            float acc[4][4];
#pragma unroll
            for (int i = 0; i < 4; i++)
#pragma unroll
                for (int e = 0; e < 4; e++) acc[i][e] = 0.0f;

            stream_gemm<2>(smb, g_Uimg + (size_t)bm * NKT * ATILE, SW_WB, 8192, acc);

#pragma unroll
            for (int mt = 0; mt < 2; mt++)
#pragma unroll
                for (int nt = 0; nt < 2; nt++) {
                    const int c = bn * 64 + wn * 16 + nt * 8 + tg * 2;
#pragma unroll
                    for (int h2 = 0; h2 < 2; h2++) {
                        const int irow = wm * 32 + mt * 16 + g + h2 * 8;
                        const int row = bm * 128 + irow;
                        float v0 = acc[mt * 2 + nt][h2 * 2 + 0];
                        float v1 = acc[mt * 2 + nt][h2 * 2 + 1];
                        const size_t xb = ((size_t)row * TT_ + t) * 1536;
                        float2 xp = unpack_h2(*(const uint32_t*)(g_xp16 + xb + 1024 + c));
                        float2 zv = *(const float2*)(g_z + (size_t)row * 512 + c);
                        float2 hv = *(const float2*)(g_h + (size_t)row * 512 + c);
                        float hn0 = zv.x * hv.x + (1.0f - zv.x) * tanhf(v0 + xp.x);
                        float hn1 = zv.y * hv.y + (1.0f - zv.y) * tanhf(v1 + xp.y);
                        float2 hn; hn.x = hn0; hn.y = hn1;
                        *(float2*)(g_h + (size_t)row * 512 + c) = hn;
                        *(float2*)(out + ((size_t)row * TT_ + t) * 512 + c) = hn;
                        const size_t blk = ((size_t)bm * NKT + (c >> 6)) * ATILE;
                        const uint32_t off = swz((uint32_t)irow * 128 + (uint32_t)(c & 63) * 2);
                        *(uint32_t*)(g_Himg + blk + off) = pack_hi(hn0, hn1);
                    }
                }
        }

        if (t < TT_ - 1) prefA(t + 1);   // next step's phase-A operands during barrier
        group_bar(bm);
    }
}

// ---------------- launch ----------------
extern "C" void kernel_launch(void* const* d_in, const int* in_sizes, int n_in,
                              void* d_out, int out_size) {
    const float* X   = (const float*)d_in[0];
    const float* Wzx = (const float*)d_in[1];
    const float* Wzh = (const float*)d_in[2];
    const float* Wrx = (const float*)d_in[3];
    const float* Wrh = (const float*)d_in[4];
    const float* Whx = (const float*)d_in[5];
    const float* Whh = (const float*)d_in[6];
    const float* bz  = (const float*)d_in[7];
    const float* br  = (const float*)d_in[8];
    const float* bh  = (const float*)d_in[9];
    float* out = (float*)d_out;

    const int SMEM0 = 2 * 32768;              // 65536 for gemm0
    const int SMEMS = 131072 + 65536 + 32768; // 229376 for step_all
    cudaFuncSetAttribute((const void*)gemm0_k, cudaFuncAttributeMaxDynamicSharedMemorySize, SMEM0);
    cudaFuncSetAttribute((const void*)step_all, cudaFuncAttributeMaxDynamicSharedMemorySize, SMEMS);

    prep_weights<<<1536, 256>>>(Wzx, Wzh, Wrx, Wrh, Whx, Whh, bz, br, bh);
    prep_x<<<32768, 256>>>(X);

    gemm0_k<<<dim3(12, 1024), 512, SMEM0>>>(out);

    step_all<<<128, 512, SMEMS>>>(out);
}

// round 16
// speedup vs baseline: 1.6854x; 1.0996x over previous
#include <cuda_runtime.h>
#include <cuda_fp16.h>
#include <cstdint>
#include <math.h>

#define D_  512
#define NB_ 2048
#define TT_ 64
#define MT_ (NB_*TT_)

#define ATILE 16384        // 128r x 64k fp16 hi-only, SW128
#define NKT 8

__device__ __align__(128) unsigned char g_Ximg[(size_t)1024 * NKT * ATILE];
__device__ __align__(128) unsigned char g_W1img[12 * NKT * ATILE];   // hi-only
__device__ __align__(128) unsigned char g_Wgimg[8 * NKT * ATILE];    // hi-only
__device__ __align__(128) unsigned char g_Whimg[4 * NKT * ATILE];    // hi-only
__device__ __align__(128) unsigned char g_Himg[16 * NKT * ATILE];
__device__ __align__(128) unsigned char g_Uimg[16 * NKT * ATILE];
__device__ __align__(16) __half g_xp16[(size_t)MT_ * 1536];          // fp16 xproj
__device__ __align__(16) float g_bias[1536];
__device__ __align__(16) float g_h[NB_ * D_];
__device__ __align__(16) float g_z[NB_ * D_];
__device__ __align__(128) unsigned g_gc[16 * 32];
__device__ __align__(128) unsigned g_gf[16 * 32];

// ---------------- helpers ----------------
__device__ __forceinline__ uint32_t swz(uint32_t o) { return o ^ ((o >> 3) & 0x70); }

__device__ __forceinline__ uint32_t pack_hi(float x0, float x1) {
    __half2 h = __floats2half2_rn(x0, x1);
    return *reinterpret_cast<uint32_t*>(&h);
}
__device__ __forceinline__ float2 unpack_h2(uint32_t u) {
    __half2 h = *reinterpret_cast<__half2*>(&u);
    return __half22float2(h);
}

__device__ __forceinline__ void aimg_write(unsigned char* img, int rt, int kt,
                                           int irow, int jj, float x0, float x1) {
    size_t blk = ((size_t)rt * NKT + kt) * ATILE;
    uint32_t off = swz((uint32_t)irow * 128 + (uint32_t)jj * 4);
    *(uint32_t*)(img + blk + off) = pack_hi(x0, x1);
}

__device__ __forceinline__ uint32_t smem_u32(const void* p) {
    uint32_t r;
    asm("{ .reg .u64 t; cvta.to.shared.u64 t, %1; cvt.u32.u64 %0, t; }" : "=r"(r) : "l"(p));
    return r;
}
__device__ __forceinline__ void cpa16(uint32_t dst, const void* src) {
    asm volatile("cp.async.cg.shared.global [%0], [%1], 16;" :: "r"(dst), "l"(src));
}
__device__ __forceinline__ void cpa_commit() { asm volatile("cp.async.commit_group;" ::: "memory"); }
__device__ __forceinline__ void cpa_wait0() { asm volatile("cp.async.wait_group 0;" ::: "memory"); }
__device__ __forceinline__ void pref_l2(const void* p) {
    asm volatile("prefetch.global.L2 [%0];" :: "l"(p));
}

__device__ __forceinline__ void ldsm4(uint32_t* r, uint32_t addr) {
    asm volatile("ldmatrix.sync.aligned.m8n8.x4.shared.b16 {%0,%1,%2,%3}, [%4];"
                 : "=r"(r[0]), "=r"(r[1]), "=r"(r[2]), "=r"(r[3]) : "r"(addr));
}
__device__ __forceinline__ void mma16(float* d, const uint32_t* a, const uint32_t* b) {
    asm volatile(
        "mma.sync.aligned.m16n8k16.row.col.f32.f16.f16.f32 "
        "{%0,%1,%2,%3},{%4,%5,%6,%7},{%8,%9},{%0,%1,%2,%3};"
        : "+f"(d[0]), "+f"(d[1]), "+f"(d[2]), "+f"(d[3])
        : "r"(a[0]), "r"(a[1]), "r"(a[2]), "r"(a[3]), "r"(b[0]), "r"(b[1]));
}

// ---- fast gates via HW tanh.approx (sm_75+ baseline ISA) ----
__device__ __forceinline__ float tanha(float x) {
    float r;
    asm("tanh.approx.f32 %0, %1;" : "=f"(r) : "f"(x));
    return r;
}
__device__ __forceinline__ float sigmoidf_(float x) {
    return fmaf(0.5f, tanha(0.5f * x), 0.5f);
}

// ---------------- prep ----------------
__global__ void prep_weights(const float* __restrict__ Wzx, const float* __restrict__ Wzh,
                             const float* __restrict__ Wrx, const float* __restrict__ Wrh,
                             const float* __restrict__ Whx, const float* __restrict__ Whh,
                             const float* __restrict__ bz, const float* __restrict__ br,
                             const float* __restrict__ bh) {
    int i = blockIdx.x * 256 + threadIdx.x;
    int n = i >> 8, jp = i & 255;
    int kt = jp >> 5, jj = jp & 31, k = jp * 2;
    {
        const float* s = (n < 512) ? Wzx : (n < 1024 ? Wrx : Whx);
        int nn = (n < 512) ? n : (n < 1024 ? n - 512 : n - 1024);
        aimg_write(g_W1img, n >> 7, kt, n & 127, jj, s[nn * 512 + k], s[nn * 512 + k + 1]);
    }
    if (n < 1024) {
        const float* s = (n < 512) ? Wzh : Wrh;
        int nn = n & 511;
        aimg_write(g_Wgimg, n >> 7, kt, n & 127, jj, s[nn * 512 + k], s[nn * 512 + k + 1]);
    }
    if (n < 512)
        aimg_write(g_Whimg, n >> 7, kt, n & 127, jj, Whh[n * 512 + k], Whh[n * 512 + k + 1]);
    if (i < 1536) g_bias[i] = (i < 512) ? bz[i] : (i < 1024 ? br[i - 512] : bh[i - 1024]);
    if (i < NB_ * D_ / 4) ((float4*)g_h)[i] = make_float4(0.f, 0.f, 0.f, 0.f);
    if (i < 16 * NKT * ATILE / 16) ((uint4*)g_Himg)[i] = make_uint4(0, 0, 0, 0);
}

__global__ void prep_x(const float* __restrict__ X) {
    int i = blockIdx.x * 256 + threadIdx.x;      // 32768 blocks; 8 cols per thread
    int row = i >> 6, jq = i & 63;
    const float* src = X + (size_t)row * 512 + jq * 8;
    float4 a = *(const float4*)src, b = *(const float4*)(src + 4);
    uint4 v = make_uint4(pack_hi(a.x, a.y), pack_hi(a.z, a.w),
                         pack_hi(b.x, b.y), pack_hi(b.z, b.w));
    int kt = jq >> 3;
    size_t blk = ((size_t)(row >> 7) * NKT + kt) * ATILE;
    uint32_t off = swz((uint32_t)(row & 127) * 128 + (uint32_t)(jq & 7) * 16);
    *(uint4*)(g_Ximg + blk + off) = v;
}

// ---------------- gemm0 core ----------
__device__ __forceinline__ void gemm0_core(uint32_t smb,
                                           const unsigned char* __restrict__ Asrc0,
                                           const unsigned char* __restrict__ Bsrc0,
                                           float (*acc)[4]) {
    constexpr int SBUF = 32768;
    const int tid = threadIdx.x, lane = tid & 31, warp = tid >> 5;
    const int wm = warp >> 2, wn = warp & 3;
    const int rx = (lane & 7) << 4;
    const int colA = (lane >> 4) << 4;
    const int colB = ((lane >> 3) & 1) << 4;
    int rA[2], rB[2];
#pragma unroll
    for (int mt = 0; mt < 2; mt++)
        rA[mt] = (wm * 32 + mt * 16 + (lane & 15)) * 128;
#pragma unroll
    for (int p = 0; p < 2; p++)
        rB[p] = (wn * 32 + p * 16 + (lane & 7) + ((lane >> 4) << 3)) * 128;

    auto docopy = [&](int kt) {
        const uint32_t da = smb + (kt & 1) * SBUF;
        const unsigned char* sa = Asrc0 + (size_t)kt * ATILE;
        cpa16(da + tid * 16, sa + (size_t)tid * 16);
        cpa16(da + (tid + 512) * 16, sa + (size_t)(tid + 512) * 16);
        const uint32_t db = da + 16384;
        const unsigned char* sb = Bsrc0 + (size_t)kt * ATILE;
        cpa16(db + tid * 16, sb + (size_t)tid * 16);
        cpa16(db + (tid + 512) * 16, sb + (size_t)(tid + 512) * 16);
    };

    docopy(0); cpa_commit();
#pragma unroll 1
    for (int kt = 0; kt < NKT; kt++) {
        cpa_wait0();
        __syncthreads();
        if (kt < NKT - 1) { docopy(kt + 1); cpa_commit(); }

        const uint32_t sA = smb + (kt & 1) * SBUF;
        const uint32_t sB = sA + 16384;
#pragma unroll
        for (int k16 = 0; k16 < 4; k16++) {
            uint32_t Ah[2][4];
#pragma unroll
            for (int mt = 0; mt < 2; mt++)
                ldsm4(Ah[mt], sA + rA[mt] + ((k16 * 32 + colA) ^ rx));
            uint32_t Bh[4][2];
#pragma unroll
            for (int p = 0; p < 2; p++) {
                uint32_t r4[4];
                ldsm4(r4, sB + rB[p] + ((k16 * 32 + colB) ^ rx));
                Bh[2 * p][0] = r4[0]; Bh[2 * p][1] = r4[1];
                Bh[2 * p + 1][0] = r4[2]; Bh[2 * p + 1][1] = r4[3];
            }
#pragma unroll
            for (int mt = 0; mt < 2; mt++)
#pragma unroll
                for (int nt = 0; nt < 4; nt++) mma16(acc[mt * 4 + nt], Ah[mt], Bh[nt]);
        }
    }
}

// ---------------- phase-1 kernel ----------------
__global__ __launch_bounds__(512, 1) void gemm0_k(float* __restrict__ out) {
    extern __shared__ __align__(1024) unsigned char sm[];
    const uint32_t smb = smem_u32(sm);
    const int tid = threadIdx.x, lane = tid & 31, warp = tid >> 5;
    const int wm = warp >> 2, wn = warp & 3, g = lane >> 2, tg = lane & 3;
    const int bn = blockIdx.x, bm = blockIdx.y;

    float acc[8][4];
#pragma unroll
    for (int i = 0; i < 8; i++)
#pragma unroll
        for (int e = 0; e < 4; e++) acc[i][e] = 0.0f;

    gemm0_core(smb, g_Ximg + (size_t)bm * NKT * ATILE,
               g_W1img + (size_t)bn * NKT * ATILE, acc);

    const int cbase = bn * 128 + wn * 32;
#pragma unroll
    for (int mt = 0; mt < 2; mt++)
#pragma unroll
        for (int nt = 0; nt < 4; nt++) {
            const int c = cbase + nt * 8 + tg * 2;
            float2 b = *(const float2*)(g_bias + c);
#pragma unroll
            for (int h2 = 0; h2 < 2; h2++) {
                const int row = bm * 128 + wm * 32 + mt * 16 + g + h2 * 8;
                float o0 = acc[mt * 4 + nt][h2 * 2 + 0] + b.x;
                float o1 = acc[mt * 4 + nt][h2 * 2 + 1] + b.y;
                *(uint32_t*)(g_xp16 + (size_t)row * 1536 + c) = pack_hi(o0, o1);
            }
        }
}

// ---------------- per-group (8-CTA) atomic barrier (acq_rel fences) ----------------
__device__ __forceinline__ void group_bar(int gid) {
    asm volatile("fence.acq_rel.gpu;" ::: "memory");
    __syncthreads();
    if (threadIdx.x == 0) {
        unsigned entry;
        asm volatile("ld.acquire.gpu.u32 %0, [%1];" : "=r"(entry) : "l"(&g_gf[gid * 32]) : "memory");
        unsigned tk = atomicAdd(&g_gc[gid * 32], 1);
        if (tk == 7) {
            g_gc[gid * 32] = 0;
            asm volatile("fence.acq_rel.gpu;" ::: "memory");
            atomicAdd(&g_gf[gid * 32], 1);
        } else {
            unsigned cur;
            do {
                asm volatile("ld.acquire.gpu.u32 %0, [%1];" : "=r"(cur) : "l"(&g_gf[gid * 32]) : "memory");
            } while (cur == entry);
        }
    }
    __syncthreads();
}

// ---------------- persistent recurrence ----------------
#define SW_WA 0
#define SW_WB 131072
#define SW_RING 196608

template <int NT>
__device__ __forceinline__ void stream_gemm(uint32_t smb,
                                            const unsigned char* __restrict__ Asrc0,
                                            uint32_t wbase, uint32_t wstride,
                                            float (*acc)[4]) {
    const int tid = threadIdx.x, lane = tid & 31, warp = tid >> 5;
    const int wm = warp >> 2, wn = warp & 3;
    const int rx = (lane & 7) << 4;
    const int colA = (lane >> 4) << 4;
    const int colB = ((lane >> 3) & 1) << 4;
    int rA[2], rB[NT / 2];
#pragma unroll
    for (int mt = 0; mt < 2; mt++)
        rA[mt] = (wm * 32 + mt * 16 + (lane & 15)) * 128;
#pragma unroll
    for (int p = 0; p < NT / 2; p++)
        rB[p] = (wn * (NT * 8) + p * 16 + (lane & 7) + ((lane >> 4) << 3)) * 128;

    auto docopy = [&](int kt) {
        const uint32_t da = smb + SW_RING + (kt & 1) * 16384;
        const unsigned char* sa = Asrc0 + (size_t)kt * ATILE;
        cpa16(da + tid * 16, sa + (size_t)tid * 16);
        cpa16(da + (tid + 512) * 16, sa + (size_t)(tid + 512) * 16);
    };

    docopy(0); cpa_commit();
#pragma unroll 1
    for (int kt = 0; kt < NKT; kt++) {
        cpa_wait0();
        __syncthreads();
        if (kt < NKT - 1) { docopy(kt + 1); cpa_commit(); }

        const uint32_t sA = smb + SW_RING + (kt & 1) * 16384;
        const uint32_t sW = smb + wbase + kt * wstride;
#pragma unroll
        for (int k16 = 0; k16 < 4; k16++) {
            uint32_t Ah[2][4];
#pragma unroll
            for (int mt = 0; mt < 2; mt++)
                ldsm4(Ah[mt], sA + rA[mt] + ((k16 * 32 + colA) ^ rx));
            uint32_t Bh[NT][2];
#pragma unroll
            for (int p = 0; p < NT / 2; p++) {
                uint32_t r4[4];
                ldsm4(r4, sW + rB[p] + ((k16 * 32 + colB) ^ rx));
                Bh[2 * p][0] = r4[0]; Bh[2 * p][1] = r4[1];
                Bh[2 * p + 1][0] = r4[2]; Bh[2 * p + 1][1] = r4[3];
            }
#pragma unroll
            for (int mt = 0; mt < 2; mt++)
#pragma unroll
                for (int nt = 0; nt < NT; nt++) mma16(acc[mt * NT + nt], Ah[mt], Bh[nt]);
        }
    }
}

__global__ __launch_bounds__(512, 1) void step_all(float* __restrict__ out) {
    extern __shared__ __align__(1024) unsigned char sm[];
    const uint32_t smb = smem_u32(sm);
    const int tid = threadIdx.x, lane = tid & 31, warp = tid >> 5;
    const int wm = warp >> 2, wn = warp & 3, g = lane >> 2, tg = lane & 3;
    const int bm = blockIdx.x >> 3, bn = blockIdx.x & 7;

    // full-coverage L2 prefetch of phase-A xproj lines (256 x 128B)
    auto prefA = [&](int t) {
        if (tid < 256) {
            const int row = bm * 128 + (tid >> 1);
            pref_l2((const char*)g_xp16 + ((size_t)row * TT_ + t) * 3072 + bn * 256 + (tid & 1) * 128);
        }
    };
    // phase-B xproj lines (128 x 128B)
    auto prefB = [&](int t) {
        if (tid < 128) {
            const int row = bm * 128 + tid;
            pref_l2((const char*)g_xp16 + ((size_t)row * TT_ + t) * 3072 + 2048 + bn * 128);
        }
    };

    // ---- resident weight load ----
    {
        const unsigned char* wg = g_Wgimg + (size_t)bn * NKT * ATILE;
#pragma unroll
        for (int i = 0; i < 16; i++)
            cpa16(smb + SW_WA + (tid + i * 512) * 16, wg + (size_t)(tid + i * 512) * 16);
        const unsigned char* wh = g_Whimg + (size_t)(bn >> 1) * NKT * ATILE + (bn & 1) * 8192;
#pragma unroll
        for (int kt = 0; kt < NKT; kt++)
            cpa16(smb + SW_WB + kt * 8192 + tid * 16, wh + (size_t)kt * ATILE + tid * 16);
        cpa_commit();
        prefA(0);
        cpa_wait0();
        __syncthreads();
    }

#pragma unroll 1
    for (int t = 0; t < TT_; t++) {
        // ===== phase A: [z|r] = h @ Wg^T =====
        {
            prefB(t);   // long flight time: consumed after phase-A + barrier + B GEMM

            float acc[8][4];
#pragma unroll
            for (int i = 0; i < 8; i++)
#pragma unroll
                for (int e = 0; e < 4; e++) acc[i][e] = 0.0f;

            stream_gemm<4>(smb, g_Himg + (size_t)bm * NKT * ATILE, SW_WA, 16384, acc);

            const int cbase = bn * 128 + wn * 32;
#pragma unroll
            for (int mt = 0; mt < 2; mt++)
#pragma unroll
                for (int nt = 0; nt < 4; nt++) {
                    const int c = cbase + nt * 8 + tg * 2;
#pragma unroll
                    for (int h2 = 0; h2 < 2; h2++) {
                        const int irow = wm * 32 + mt * 16 + g + h2 * 8;
                        const int row = bm * 128 + irow;
                        float v0 = acc[mt * 4 + nt][h2 * 2 + 0];
                        float v1 = acc[mt * 4 + nt][h2 * 2 + 1];
                        const size_t xb = ((size_t)row * TT_ + t) * 1536;
                        float2 xp = unpack_h2(*(const uint32_t*)(g_xp16 + xb + c));
                        if (cbase < 512) {
                            float2 zv;
                            zv.x = sigmoidf_(v0 + xp.x);
                            zv.y = sigmoidf_(v1 + xp.y);
                            *(float2*)(g_z + (size_t)row * 512 + c) = zv;
                        } else {
                            const int c2 = c - 512;
                            float2 hv = *(const float2*)(g_h + (size_t)row * 512 + c2);
                            float u0 = sigmoidf_(v0 + xp.x) * hv.x;
                            float u1 = sigmoidf_(v1 + xp.y) * hv.y;
                            const size_t blk = ((size_t)bm * NKT + (c2 >> 6)) * ATILE;
                            const uint32_t off = swz((uint32_t)irow * 128 + (uint32_t)(c2 & 63) * 2);
                            *(uint32_t*)(g_Uimg + blk + off) = pack_hi(u0, u1);
                        }
                    }
                }
        }

        group_bar(bm);

        // ===== phase B: h_tilde = u @ Whh^T ; h update =====
        {
            if (t < TT_ - 1) prefA(t + 1);   // long flight: consumed after B + barrier + A GEMM

            float acc[4][4];
#pragma unroll
            for (int i = 0; i < 4; i++)
#pragma unroll
                for (int e = 0; e < 4; e++) acc[i][e] = 0.0f;

            stream_gemm<2>(smb, g_Uimg + (size_t)bm * NKT * ATILE, SW_WB, 8192, acc);

#pragma unroll
            for (int mt = 0; mt < 2; mt++)
#pragma unroll
                for (int nt = 0; nt < 2; nt++) {
                    const int c = bn * 64 + wn * 16 + nt * 8 + tg * 2;
#pragma unroll
                    for (int h2 = 0; h2 < 2; h2++) {
                        const int irow = wm * 32 + mt * 16 + g + h2 * 8;
                        const int row = bm * 128 + irow;
                        float v0 = acc[mt * 2 + nt][h2 * 2 + 0];
                        float v1 = acc[mt * 2 + nt][h2 * 2 + 1];
                        const size_t xb = ((size_t)row * TT_ + t) * 1536;
                        float2 xp = unpack_h2(*(const uint32_t*)(g_xp16 + xb + 1024 + c));
                        float2 zv = *(const float2*)(g_z + (size_t)row * 512 + c);
                        float2 hv = *(const float2*)(g_h + (size_t)row * 512 + c);
                        float hn0 = zv.x * hv.x + (1.0f - zv.x) * tanha(v0 + xp.x);
                        float hn1 = zv.y * hv.y + (1.0f - zv.y) * tanha(v1 + xp.y);
                        float2 hn; hn.x = hn0; hn.y = hn1;
                        *(float2*)(g_h + (size_t)row * 512 + c) = hn;
                        __stcs((float2*)(out + ((size_t)row * TT_ + t) * 512 + c), hn);
                        const size_t blk = ((size_t)bm * NKT + (c >> 6)) * ATILE;
                        const uint32_t off = swz((uint32_t)irow * 128 + (uint32_t)(c & 63) * 2);
                        *(uint32_t*)(g_Himg + blk + off) = pack_hi(hn0, hn1);
                    }
                }
        }

        group_bar(bm);
    }
}

// ---------------- launch ----------------
extern "C" void kernel_launch(void* const* d_in, const int* in_sizes, int n_in,
                              void* d_out, int out_size) {
    const float* X   = (const float*)d_in[0];
    const float* Wzx = (const float*)d_in[1];
    const float* Wzh = (const float*)d_in[2];
    const float* Wrx = (const float*)d_in[3];
    const float* Wrh = (const float*)d_in[4];
    const float* Whx = (const float*)d_in[5];
    const float* Whh = (const float*)d_in[6];
    const float* bz  = (const float*)d_in[7];
    const float* br  = (const float*)d_in[8];
    const float* bh  = (const float*)d_in[9];
    float* out = (float*)d_out;

    const int SMEM0 = 2 * 32768;              // 65536 for gemm0
    const int SMEMS = 131072 + 65536 + 32768; // 229376 for step_all
    cudaFuncSetAttribute((const void*)gemm0_k, cudaFuncAttributeMaxDynamicSharedMemorySize, SMEM0);
    cudaFuncSetAttribute((const void*)step_all, cudaFuncAttributeMaxDynamicSharedMemorySize, SMEMS);

    prep_weights<<<1536, 256>>>(Wzx, Wzh, Wrx, Wrh, Whx, Whh, bz, br, bh);
    prep_x<<<32768, 256>>>(X);

    gemm0_k<<<dim3(12, 1024), 512, SMEM0>>>(out);

    step_all<<<128, 512, SMEMS>>>(out);
}